// round 6
// baseline (speedup 1.0000x reference)
#include <cuda_runtime.h>
#include <math.h>

// Problem constants
#define Bv    32
#define Nv    4096
#define INPv  512
#define Sv    8
#define Dv    256
#define Hv    512
#define ROWSv (Bv*Nv)   // 131072
#define SRv   (Bv*Sv)   // 256

// ---------------- scratch (static device globals; no allocs allowed) ----------------
__device__ __align__(16) float g_k[33554432];      // [ROWS][256]  128 MB
__device__ __align__(16) float g_v[33554432];      // [ROWS][256]  128 MB
__device__ __align__(16) float g_stats[262144];    // [ROWS][2] mean,rstd
__device__ __align__(16) float g_wsum[512];        // colsum of [Wk|Wv]
__device__ __align__(16) float g_slots[65536];     // [256][256]
__device__ __align__(16) float g_sln[65536];
__device__ __align__(16) float g_q[65536];
__device__ __align__(16) float g_upd[65536];
__device__ __align__(16) float g_colsum[256];
__device__ __align__(16) float g_gx[196608];       // [256][768]
__device__ __align__(16) float g_gh[196608];
__device__ __align__(16) float g_h1[131072];       // [256][512]
__device__ __align__(16) float g_y[65536];

// ---------------- LN stats: mean/rstd per input row of 512 ----------------
__global__ void ln_stats_kernel(const float* __restrict__ X) {
    int warp = threadIdx.x >> 5, lane = threadIdx.x & 31;
    int row  = blockIdx.x * 8 + warp;
    const float* xr = X + (size_t)row * INPv;
    float s = 0.f, s2 = 0.f;
#pragma unroll
    for (int j = 0; j < 4; j++) {
        float4 v4 = *(const float4*)(xr + lane * 4 + 128 * j);
        s  += v4.x + v4.y + v4.z + v4.w;
        s2 += v4.x * v4.x + v4.y * v4.y + v4.z * v4.z + v4.w * v4.w;
    }
#pragma unroll
    for (int off = 16; off; off >>= 1) {
        s  += __shfl_down_sync(0xffffffffu, s,  off);
        s2 += __shfl_down_sync(0xffffffffu, s2, off);
    }
    if (!lane) {
        float m   = s * (1.f / INPv);
        float var = s2 * (1.f / INPv) - m * m;
        g_stats[row * 2]     = m;
        g_stats[row * 2 + 1] = rsqrtf(var + 1e-5f);
    }
}

// ---------------- column sums of Wk|Wv (for LN folding) ----------------
__global__ void wsum_kernel(const float* __restrict__ Wk, const float* __restrict__ Wv) {
    int j = threadIdx.x;                 // 512 threads
    const float* W = (j < 256) ? Wk : Wv;
    int c = j & 255;
    float s = 0.f;
    for (int k = 0; k < INPv; k++) s += W[k * 256 + c];
    g_wsum[j] = s;
}

// ---------------- fused projection GEMM: k|v = LN(x) @ [Wk|Wv] ----------------
// 128x128x16 tiles, 256 threads, 8x8 micro-tile. Epilogue applies LN fold.
__global__ __launch_bounds__(256, 2)
void proj_kernel(const float* __restrict__ X,
                 const float* __restrict__ Wk, const float* __restrict__ Wv) {
    __shared__ float As[16 * 132];
    __shared__ float Bs[16 * 132];
    int bn = blockIdx.x;                 // 0..3 (cols of fused 512)
    int bm = blockIdx.y;                 // 0..1023
    const float* Wb = (bn < 2) ? Wk : Wv;
    int wcol0 = (bn & 1) * 128;
    int row0  = bm * 128;
    int tid = threadIdx.x;
    int ty = tid >> 4, tx = tid & 15;
    float acc[8][8] = {};

    for (int k0 = 0; k0 < 512; k0 += 16) {
#pragma unroll
        for (int l = 0; l < 2; l++) {          // A: 128 rows x 16 k, transposed into smem
            int t = tid + l * 256;
            int row = t >> 2, q = t & 3;
            float4 av = *(const float4*)(X + (size_t)(row0 + row) * 512 + k0 + q * 4);
            int kk = q * 4;
            As[(kk + 0) * 132 + row] = av.x;
            As[(kk + 1) * 132 + row] = av.y;
            As[(kk + 2) * 132 + row] = av.z;
            As[(kk + 3) * 132 + row] = av.w;
        }
#pragma unroll
        for (int l = 0; l < 2; l++) {          // B: 16 k x 128 n
            int t = tid + l * 256;
            int kk = t >> 5, q = t & 31;
            float4 bv = *(const float4*)(Wb + (size_t)(k0 + kk) * 256 + wcol0 + q * 4);
            *(float4*)(Bs + kk * 132 + q * 4) = bv;
        }
        __syncthreads();
#pragma unroll
        for (int kk = 0; kk < 16; kk++) {
            float4 a0 = *(const float4*)(As + kk * 132 + ty * 4);
            float4 a1 = *(const float4*)(As + kk * 132 + 64 + ty * 4);
            float4 b0 = *(const float4*)(Bs + kk * 132 + tx * 4);
            float4 b1 = *(const float4*)(Bs + kk * 132 + 64 + tx * 4);
            float av[8] = {a0.x, a0.y, a0.z, a0.w, a1.x, a1.y, a1.z, a1.w};
            float bw[8] = {b0.x, b0.y, b0.z, b0.w, b1.x, b1.y, b1.z, b1.w};
#pragma unroll
            for (int i = 0; i < 8; i++)
#pragma unroll
                for (int j = 0; j < 8; j++)
                    acc[i][j] += av[i] * bw[j];
        }
        __syncthreads();
    }
#pragma unroll
    for (int i = 0; i < 8; i++) {
        int r = row0 + ((i < 4) ? ty * 4 + i : 64 + ty * 4 + i - 4);
        float mean = g_stats[r * 2];
        float rstd = g_stats[r * 2 + 1];
        float mr = mean * rstd;
#pragma unroll
        for (int j = 0; j < 8; j++) {
            int cl = (j < 4) ? tx * 4 + j : 64 + tx * 4 + j - 4;
            int cg = bn * 128 + cl;
            float val = rstd * acc[i][j] - mr * g_wsum[cg];
            if (cg < 256) g_k[(size_t)r * 256 + cg] = val;
            else          g_v[(size_t)r * 256 + cg - 256] = val;
        }
    }
}

// ---------------- slots init ----------------
__global__ void init_slots_kernel(const float* __restrict__ noise,
                                  const float* __restrict__ mu,
                                  const float* __restrict__ ls) {
    int i = blockIdx.x * 256 + threadIdx.x;   // 65536
    int d = i & 255;
    g_slots[i] = mu[d] + expf(ls[d]) * noise[i];
}

// ---------------- block LayerNorm over 256 (blockDim=256) ----------------
__device__ __forceinline__ float block_ln256(float v) {
    __shared__ float red[66];
    float s = v, s2 = v * v;
    int lane = threadIdx.x & 31, warp = threadIdx.x >> 5;
#pragma unroll
    for (int off = 16; off; off >>= 1) {
        s  += __shfl_down_sync(0xffffffffu, s,  off);
        s2 += __shfl_down_sync(0xffffffffu, s2, off);
    }
    if (!lane) { red[warp] = s; red[32 + warp] = s2; }
    __syncthreads();
    if (threadIdx.x == 0) {
        float ts = 0.f, t2 = 0.f;
#pragma unroll
        for (int i = 0; i < 8; i++) { ts += red[i]; t2 += red[32 + i]; }
        float m   = ts * (1.f / 256.f);
        float var = t2 * (1.f / 256.f) - m * m;
        red[64] = m;
        red[65] = rsqrtf(var + 1e-5f);
    }
    __syncthreads();
    return (v - red[64]) * red[65];
}

// ---------------- slots LN + q = s_ln @ Wq ----------------
__global__ void slot_ln_q_kernel(const float* __restrict__ Wq) {
    __shared__ float sln[256];
    int row = blockIdx.x, t = threadIdx.x;
    float v  = g_slots[row * 256 + t];
    float nv = block_ln256(v);
    g_sln[row * 256 + t] = nv;
    sln[t] = nv;
    __syncthreads();
    float acc = 0.f;
#pragma unroll 4
    for (int k = 0; k < 256; k++) acc += sln[k] * Wq[k * 256 + t];
    g_q[row * 256 + t] = acc;
}

// ---------------- zero accumulators ----------------
__global__ void zero_kernel() {
    int i = blockIdx.x * 256 + threadIdx.x;
    g_upd[i] = 0.f;
    if (i < 256) g_colsum[i] = 0.f;
}

// ---------------- fused attention + updates ----------------
// grid (32 n-chunks, 32 batches), 256 threads.
// phase1: warps compute softmax(k.q/16)+eps into smem p[128][8]; colsum atomics
// phase2: thread t owns d=t; accumulates p^T v partials; atomics into g_upd
__global__ __launch_bounds__(256)
void attn_upd_kernel() {
    __shared__ float qs[2048];       // [8][256]
    __shared__ float ps[128 * 8];
    int b  = blockIdx.y;
    int n0 = blockIdx.x * 128;
    int tid = threadIdx.x;
    int warp = tid >> 5, lane = tid & 31;

    for (int i = tid; i < 2048; i += 256) qs[i] = g_q[(size_t)b * 2048 + i];
    __syncthreads();

    float csum[8] = {};
#pragma unroll
    for (int g = 0; g < 4; g++) {
        int nb = n0 + warp * 16 + g * 4;
        const float* k0p = g_k + ((size_t)(b * Nv + nb)) * 256;
        float part[4][8] = {};
#pragma unroll
        for (int j = 0; j < 8; j++) {
            int d = lane + 32 * j;
            float kv0 = k0p[d];
            float kv1 = k0p[256 + d];
            float kv2 = k0p[512 + d];
            float kv3 = k0p[768 + d];
#pragma unroll
            for (int s = 0; s < 8; s++) {
                float qv = qs[s * 256 + d];
                part[0][s] += kv0 * qv;
                part[1][s] += kv1 * qv;
                part[2][s] += kv2 * qv;
                part[3][s] += kv3 * qv;
            }
        }
#pragma unroll
        for (int i = 0; i < 4; i++)
#pragma unroll
            for (int s = 0; s < 8; s++)
#pragma unroll
                for (int off = 16; off; off >>= 1)
                    part[i][s] += __shfl_down_sync(0xffffffffu, part[i][s], off);
        if (lane == 0) {
#pragma unroll
            for (int i = 0; i < 4; i++) {
                const float scale = 0.0625f;   // 1/sqrt(256)
                float m = -1e30f;
#pragma unroll
                for (int s = 0; s < 8; s++) m = fmaxf(m, part[i][s] * scale);
                float e[8], sum = 0.f;
#pragma unroll
                for (int s = 0; s < 8; s++) { e[s] = __expf(part[i][s] * scale - m); sum += e[s]; }
                float inv = 1.f / sum;
                int nl = warp * 16 + g * 4 + i;
#pragma unroll
                for (int s = 0; s < 8; s++) {
                    float p = e[s] * inv + 1e-8f;
                    ps[nl * 8 + s] = p;
                    csum[s] += p;
                }
            }
        }
    }
    if (lane == 0) {
#pragma unroll
        for (int s = 0; s < 8; s++) atomicAdd(&g_colsum[b * 8 + s], csum[s]);
    }
    __syncthreads();

    // phase 2: p^T v
    int d = tid;
    float acc[8] = {};
    const float* vb = g_v + ((size_t)(b * Nv + n0)) * 256;
    for (int n = 0; n < 128; n++) {
        float vv = vb[(size_t)n * 256 + d];
#pragma unroll
        for (int s = 0; s < 8; s++) acc[s] += ps[n * 8 + s] * vv;
    }
#pragma unroll
    for (int s = 0; s < 8; s++) atomicAdd(&g_upd[(b * 8 + s) * 256 + d], acc[s]);
}

// ---------------- divide updates by colsum ----------------
__global__ void finalize_upd_kernel() {
    int i = blockIdx.x * 256 + threadIdx.x;
    g_upd[i] = g_upd[i] / g_colsum[i >> 8];
}

// ---------------- small GEMM: C[M,N] = A[M,K] @ op(B) + bias ----------------
// TRANSB: B stored [N,K] row-major (PyTorch linear weight). 64x64x8 tiles.
template<bool TRANSB, bool RELU, bool ACCUM>
__global__ __launch_bounds__(256)
void gemm64_kernel(const float* __restrict__ A, const float* __restrict__ Bm,
                   const float* __restrict__ bias, float* __restrict__ C,
                   int M, int N, int K) {
    __shared__ float As[8 * 68];
    __shared__ float Bs[8 * 68];
    int bm = blockIdx.y * 64, bn = blockIdx.x * 64;
    int tid = threadIdx.x;
    int ty = tid >> 4, tx = tid & 15;
    float acc[4][4] = {};
    for (int k0 = 0; k0 < K; k0 += 8) {
        if (tid < 128) {
            int row = tid >> 1, part = tid & 1;
            float4 av = *(const float4*)(A + (size_t)(bm + row) * K + k0 + part * 4);
            int kk = part * 4;
            As[(kk + 0) * 68 + row] = av.x;
            As[(kk + 1) * 68 + row] = av.y;
            As[(kk + 2) * 68 + row] = av.z;
            As[(kk + 3) * 68 + row] = av.w;
        } else {
            int t2 = tid - 128;
            if (TRANSB) {
                int n = t2 >> 1, part = t2 & 1;
                float4 bv = *(const float4*)(Bm + (size_t)(bn + n) * K + k0 + part * 4);
                int kk = part * 4;
                Bs[(kk + 0) * 68 + n] = bv.x;
                Bs[(kk + 1) * 68 + n] = bv.y;
                Bs[(kk + 2) * 68 + n] = bv.z;
                Bs[(kk + 3) * 68 + n] = bv.w;
            } else {
                int kk = t2 >> 4, q = t2 & 15;
                float4 bv = *(const float4*)(Bm + (size_t)(k0 + kk) * N + bn + q * 4);
                *(float4*)(Bs + kk * 68 + q * 4) = bv;
            }
        }
        __syncthreads();
#pragma unroll
        for (int kk = 0; kk < 8; kk++) {
            float4 a = *(const float4*)(As + kk * 68 + ty * 4);
            float4 bq = *(const float4*)(Bs + kk * 68 + tx * 4);
            float av[4] = {a.x, a.y, a.z, a.w};
            float bw[4] = {bq.x, bq.y, bq.z, bq.w};
#pragma unroll
            for (int i = 0; i < 4; i++)
#pragma unroll
                for (int j = 0; j < 4; j++)
                    acc[i][j] += av[i] * bw[j];
        }
        __syncthreads();
    }
#pragma unroll
    for (int i = 0; i < 4; i++) {
        int r = bm + ty * 4 + i;
#pragma unroll
        for (int j = 0; j < 4; j++) {
            int c = bn + tx * 4 + j;
            float v = acc[i][j] + bias[c];
            if (RELU) v = fmaxf(v, 0.f);
            if (ACCUM) C[(size_t)r * N + c] += v;
            else       C[(size_t)r * N + c] = v;
        }
    }
}

// ---------------- GRU elementwise combine ----------------
__global__ void gru_combine_kernel() {
    int i = blockIdx.x * 256 + threadIdx.x;
    int row = i >> 8, d = i & 255;
    const float* gx = g_gx + row * 768;
    const float* gh = g_gh + row * 768;
    float r  = 1.f / (1.f + __expf(-(gx[d] + gh[d])));
    float z  = 1.f / (1.f + __expf(-(gx[256 + d] + gh[256 + d])));
    float nn = tanhf(gx[512 + d] + r * gh[512 + d]);
    float h  = g_sln[i];
    g_slots[i] = (1.f - z) * nn + z * h;
}

// ---------------- LN of slots -> y ----------------
__global__ void ln_y_kernel() {
    int row = blockIdx.x, t = threadIdx.x;
    float v = g_slots[row * 256 + t];
    g_y[row * 256 + t] = block_ln256(v);
}

// ---------------- copy out ----------------
__global__ void copy_out_kernel(float* __restrict__ out) {
    int i = blockIdx.x * 256 + threadIdx.x;
    out[i] = g_slots[i];
}

// =====================================================================
extern "C" void kernel_launch(void* const* d_in, const int* in_sizes, int n_in,
                              void* d_out, int out_size) {
    (void)in_sizes; (void)n_in; (void)out_size;
    const float* inputs = (const float*)d_in[0];
    const float* noise  = (const float*)d_in[1];
    const float* Wk     = (const float*)d_in[2];
    const float* Wv     = (const float*)d_in[3];
    const float* Wq     = (const float*)d_in[4];
    const float* mu     = (const float*)d_in[5];
    const float* ls     = (const float*)d_in[6];
    const float* wih    = (const float*)d_in[7];
    const float* whh    = (const float*)d_in[8];
    const float* bih    = (const float*)d_in[9];
    const float* bhh    = (const float*)d_in[10];
    const float* w1     = (const float*)d_in[11];
    const float* b1     = (const float*)d_in[12];
    const float* w2     = (const float*)d_in[13];
    const float* b2     = (const float*)d_in[14];

    float *p_upd, *p_sln, *p_y, *p_h1, *p_gx, *p_gh, *p_slots;
    cudaGetSymbolAddress((void**)&p_upd,   g_upd);
    cudaGetSymbolAddress((void**)&p_sln,   g_sln);
    cudaGetSymbolAddress((void**)&p_y,     g_y);
    cudaGetSymbolAddress((void**)&p_h1,    g_h1);
    cudaGetSymbolAddress((void**)&p_gx,    g_gx);
    cudaGetSymbolAddress((void**)&p_gh,    g_gh);
    cudaGetSymbolAddress((void**)&p_slots, g_slots);

    ln_stats_kernel<<<ROWSv / 8, 256>>>(inputs);
    wsum_kernel<<<1, 512>>>(Wk, Wv);
    proj_kernel<<<dim3(4, 1024), 256>>>(inputs, Wk, Wv);
    init_slots_kernel<<<256, 256>>>(noise, mu, ls);

    for (int it = 0; it < 3; it++) {
        slot_ln_q_kernel<<<256, 256>>>(Wq);
        zero_kernel<<<256, 256>>>();
        attn_upd_kernel<<<dim3(32, 32), 256>>>();
        finalize_upd_kernel<<<256, 256>>>();
        gemm64_kernel<true,  false, false><<<dim3(12, 4), 256>>>(p_upd, wih, bih, p_gx, 256, 768, 256);
        gemm64_kernel<true,  false, false><<<dim3(12, 4), 256>>>(p_sln, whh, bhh, p_gh, 256, 768, 256);
        gru_combine_kernel<<<256, 256>>>();
        ln_y_kernel<<<256, 256>>>();
        gemm64_kernel<false, true,  false><<<dim3(8, 4),  256>>>(p_y,  w1, b1, p_h1,    256, 512, 256);
        gemm64_kernel<false, false, true ><<<dim3(4, 4),  256>>>(p_h1, w2, b2, p_slots, 256, 256, 512);
    }
    copy_out_kernel<<<256, 256>>>((float*)d_out);
}

// round 8
// speedup vs baseline: 1.1056x; 1.1056x over previous
#include <cuda_runtime.h>
#include <math.h>
#include <stdint.h>

// Problem constants
#define Bv    32
#define Nv    4096
#define INPv  512
#define Sv    8
#define Dv    256
#define Hv    512
#define ROWSv (Bv*Nv)   // 131072
#define SRv   (Bv*Sv)   // 256

// ---------------- scratch (static device globals; no allocs allowed) ----------------
__device__ __align__(16) float g_k[33554432];      // [ROWS][256]  128 MB
__device__ __align__(16) float g_v[33554432];      // [ROWS][256]  128 MB
__device__ __align__(16) float g_stats[262144];    // [ROWS][2] mean,rstd
__device__ __align__(16) float g_wsum[512];        // colsum of [Wk|Wv]
__device__ __align__(16) float g_wt[262144];       // transposed fused W: [512 n][512 k]
__device__ __align__(16) float g_slots[65536];     // [256][256]
__device__ __align__(16) float g_sln[65536];
__device__ __align__(16) float g_q[65536];
__device__ __align__(16) float g_upd[65536];
__device__ __align__(16) float g_colsum[256];
__device__ __align__(16) float g_gx[196608];       // [256][768]
__device__ __align__(16) float g_gh[196608];
__device__ __align__(16) float g_h1[131072];       // [256][512]
__device__ __align__(16) float g_y[65536];

__device__ __forceinline__ float to_tf32(float x) {
    float r;
    asm("cvt.rna.tf32.f32 %0, %1;" : "=f"(r) : "f"(x));
    return r;
}

// ---------------- LN stats: mean/rstd per input row of 512 ----------------
__global__ void ln_stats_kernel(const float* __restrict__ X) {
    int warp = threadIdx.x >> 5, lane = threadIdx.x & 31;
    int row  = blockIdx.x * 8 + warp;
    const float* xr = X + (size_t)row * INPv;
    float s = 0.f, s2 = 0.f;
#pragma unroll
    for (int j = 0; j < 4; j++) {
        float4 v4 = *(const float4*)(xr + lane * 4 + 128 * j);
        s  += v4.x + v4.y + v4.z + v4.w;
        s2 += v4.x * v4.x + v4.y * v4.y + v4.z * v4.z + v4.w * v4.w;
    }
#pragma unroll
    for (int off = 16; off; off >>= 1) {
        s  += __shfl_down_sync(0xffffffffu, s,  off);
        s2 += __shfl_down_sync(0xffffffffu, s2, off);
    }
    if (!lane) {
        float m   = s * (1.f / INPv);
        float var = s2 * (1.f / INPv) - m * m;
        g_stats[row * 2]     = m;
        g_stats[row * 2 + 1] = rsqrtf(var + 1e-5f);
    }
}

// ---------------- column sums of Wk|Wv (for LN folding) ----------------
__global__ void wsum_kernel(const float* __restrict__ Wk, const float* __restrict__ Wv) {
    int j = threadIdx.x;                 // 512 threads
    const float* W = (j < 256) ? Wk : Wv;
    int c = j & 255;
    float s = 0.f;
    for (int k = 0; k < INPv; k++) s += W[k * 256 + c];
    g_wsum[j] = s;
}

// ---------------- transpose fused weights: g_wt[n][k] = W[k][n] ----------------
__global__ void transpose_w_kernel(const float* __restrict__ Wk, const float* __restrict__ Wv) {
    __shared__ float t[32][33];
    int n0 = blockIdx.x * 32, k0 = blockIdx.y * 32;
    int tx = threadIdx.x, ty = threadIdx.y;     // (32, 8)
    const float* W = (n0 < 256) ? Wk : Wv;
    int col0 = n0 & 255;
#pragma unroll
    for (int j = 0; j < 4; j++) {
        int k = k0 + ty + 8 * j;
        t[ty + 8 * j][tx] = W[(size_t)k * 256 + col0 + tx];
    }
    __syncthreads();
#pragma unroll
    for (int j = 0; j < 4; j++) {
        int n = n0 + ty + 8 * j;
        g_wt[(size_t)n * 512 + k0 + tx] = t[tx][ty + 8 * j];
    }
}

// ---------------- tf32 mma.sync projection: k|v = LN(x) @ [Wk|Wv] ----------------
// CTA tile 128(M) x 128(N), K chunks of 32. 8 warps in 2x4, warp tile 64x32.
// A smem [128 m][32 k] pitch 36; B smem [128 n][32 k] pitch 36 (from g_wt n-major).
#define PITCH 36

__global__ __launch_bounds__(256, 2)
void proj_mma_kernel(const float* __restrict__ X) {
    __shared__ float As[128 * PITCH];
    __shared__ float Bs[128 * PITCH];
    int n0   = blockIdx.x * 128;         // 0,128,256,384
    int row0 = blockIdx.y * 128;
    int tid  = threadIdx.x;
    int wid  = tid >> 5, lane = tid & 31;
    int warp_m = wid >> 2, warp_n = wid & 3;
    int mb = warp_m * 64, nb = warp_n * 32;
    int grp = lane >> 2, q = lane & 3;

    float acc[4][4][4];
#pragma unroll
    for (int f = 0; f < 4; f++)
#pragma unroll
        for (int g = 0; g < 4; g++)
#pragma unroll
            for (int c = 0; c < 4; c++) acc[f][g][c] = 0.f;

    for (int k0 = 0; k0 < 512; k0 += 32) {
        // load A: 128 rows x 32 k (tf32-rounded)
#pragma unroll
        for (int j = 0; j < 4; j++) {
            int fi = tid + j * 256;          // 0..1023
            int r = fi >> 3, cq = fi & 7;
            float4 v = *(const float4*)(X + (size_t)(row0 + r) * 512 + k0 + cq * 4);
            float* d = As + r * PITCH + cq * 4;
            d[0] = to_tf32(v.x); d[1] = to_tf32(v.y); d[2] = to_tf32(v.z); d[3] = to_tf32(v.w);
        }
        // load B: 128 n-rows x 32 k from g_wt
#pragma unroll
        for (int j = 0; j < 4; j++) {
            int fi = tid + j * 256;
            int r = fi >> 3, cq = fi & 7;
            float4 v = *(const float4*)(g_wt + (size_t)(n0 + r) * 512 + k0 + cq * 4);
            float* d = Bs + r * PITCH + cq * 4;
            d[0] = to_tf32(v.x); d[1] = to_tf32(v.y); d[2] = to_tf32(v.z); d[3] = to_tf32(v.w);
        }
        __syncthreads();
#pragma unroll
        for (int ks = 0; ks < 4; ks++) {
            int kc = 8 * ks + q;
            uint32_t b[4][2];
#pragma unroll
            for (int g = 0; g < 4; g++) {
                const uint32_t* bp = (const uint32_t*)(Bs + (nb + g * 8 + grp) * PITCH);
                b[g][0] = bp[kc];
                b[g][1] = bp[kc + 4];
            }
#pragma unroll
            for (int f = 0; f < 4; f++) {
                const uint32_t* a0p = (const uint32_t*)(As + (mb + f * 16 + grp) * PITCH);
                const uint32_t* a1p = (const uint32_t*)(As + (mb + f * 16 + grp + 8) * PITCH);
                uint32_t a0 = a0p[kc], a1 = a1p[kc], a2 = a0p[kc + 4], a3 = a1p[kc + 4];
#pragma unroll
                for (int g = 0; g < 4; g++) {
                    asm volatile(
                        "mma.sync.aligned.m16n8k8.row.col.f32.tf32.tf32.f32 "
                        "{%0,%1,%2,%3}, {%4,%5,%6,%7}, {%8,%9}, {%0,%1,%2,%3};"
                        : "+f"(acc[f][g][0]), "+f"(acc[f][g][1]),
                          "+f"(acc[f][g][2]), "+f"(acc[f][g][3])
                        : "r"(a0), "r"(a1), "r"(a2), "r"(a3),
                          "r"(b[g][0]), "r"(b[g][1]));
                }
            }
        }
        __syncthreads();
    }

    // epilogue: LN fold + store float2 pairs
#pragma unroll
    for (int f = 0; f < 4; f++) {
        int r0g = row0 + mb + f * 16 + grp;
        int r1g = r0g + 8;
        float m0 = g_stats[r0g * 2],     s0 = g_stats[r0g * 2 + 1];
        float m1 = g_stats[r1g * 2],     s1 = g_stats[r1g * 2 + 1];
        float mr0 = m0 * s0, mr1 = m1 * s1;
#pragma unroll
        for (int g = 0; g < 4; g++) {
            int nglob = n0 + nb + g * 8 + q * 2;
            float ws0 = g_wsum[nglob], ws1 = g_wsum[nglob + 1];
            float2 o0, o1;
            o0.x = s0 * acc[f][g][0] - mr0 * ws0;
            o0.y = s0 * acc[f][g][1] - mr0 * ws1;
            o1.x = s1 * acc[f][g][2] - mr1 * ws0;
            o1.y = s1 * acc[f][g][3] - mr1 * ws1;
            if (nglob < 256) {
                *(float2*)(g_k + (size_t)r0g * 256 + nglob) = o0;
                *(float2*)(g_k + (size_t)r1g * 256 + nglob) = o1;
            } else {
                *(float2*)(g_v + (size_t)r0g * 256 + nglob - 256) = o0;
                *(float2*)(g_v + (size_t)r1g * 256 + nglob - 256) = o1;
            }
        }
    }
}

// ---------------- slots init ----------------
__global__ void init_slots_kernel(const float* __restrict__ noise,
                                  const float* __restrict__ mu,
                                  const float* __restrict__ ls) {
    int i = blockIdx.x * 256 + threadIdx.x;   // 65536
    int d = i & 255;
    g_slots[i] = mu[d] + expf(ls[d]) * noise[i];
}

// ---------------- block LayerNorm over 256 (blockDim=256) ----------------
__device__ __forceinline__ float block_ln256(float v) {
    __shared__ float red[66];
    float s = v, s2 = v * v;
    int lane = threadIdx.x & 31, warp = threadIdx.x >> 5;
#pragma unroll
    for (int off = 16; off; off >>= 1) {
        s  += __shfl_down_sync(0xffffffffu, s,  off);
        s2 += __shfl_down_sync(0xffffffffu, s2, off);
    }
    if (!lane) { red[warp] = s; red[32 + warp] = s2; }
    __syncthreads();
    if (threadIdx.x == 0) {
        float ts = 0.f, t2 = 0.f;
#pragma unroll
        for (int i = 0; i < 8; i++) { ts += red[i]; t2 += red[32 + i]; }
        float m   = ts * (1.f / 256.f);
        float var = t2 * (1.f / 256.f) - m * m;
        red[64] = m;
        red[65] = rsqrtf(var + 1e-5f);
    }
    __syncthreads();
    return (v - red[64]) * red[65];
}

// ---------------- slots LN + q = s_ln @ Wq ----------------
__global__ void slot_ln_q_kernel(const float* __restrict__ Wq) {
    __shared__ float sln[256];
    int row = blockIdx.x, t = threadIdx.x;
    float v  = g_slots[row * 256 + t];
    float nv = block_ln256(v);
    g_sln[row * 256 + t] = nv;
    sln[t] = nv;
    __syncthreads();
    float acc = 0.f;
#pragma unroll 4
    for (int k = 0; k < 256; k++) acc += sln[k] * Wq[k * 256 + t];
    g_q[row * 256 + t] = acc;
}

// ---------------- zero accumulators ----------------
__global__ void zero_kernel() {
    int i = blockIdx.x * 256 + threadIdx.x;
    g_upd[i] = 0.f;
    if (i < 256) g_colsum[i] = 0.f;
}

// ---------------- fused attention + updates ----------------
__global__ __launch_bounds__(256)
void attn_upd_kernel() {
    __shared__ float qs[2048];       // [8][256]
    __shared__ float ps[128 * 8];
    int b  = blockIdx.y;
    int n0 = blockIdx.x * 128;
    int tid = threadIdx.x;
    int warp = tid >> 5, lane = tid & 31;

    for (int i = tid; i < 2048; i += 256) qs[i] = g_q[(size_t)b * 2048 + i];
    __syncthreads();

    float csum[8] = {};
#pragma unroll
    for (int g = 0; g < 4; g++) {
        int nb = n0 + warp * 16 + g * 4;
        const float* k0p = g_k + ((size_t)(b * Nv + nb)) * 256;
        float part[4][8] = {};
#pragma unroll
        for (int j = 0; j < 8; j++) {
            int d = lane + 32 * j;
            float kv0 = k0p[d];
            float kv1 = k0p[256 + d];
            float kv2 = k0p[512 + d];
            float kv3 = k0p[768 + d];
#pragma unroll
            for (int s = 0; s < 8; s++) {
                float qv = qs[s * 256 + d];
                part[0][s] += kv0 * qv;
                part[1][s] += kv1 * qv;
                part[2][s] += kv2 * qv;
                part[3][s] += kv3 * qv;
            }
        }
#pragma unroll
        for (int i = 0; i < 4; i++)
#pragma unroll
            for (int s = 0; s < 8; s++)
#pragma unroll
                for (int off = 16; off; off >>= 1)
                    part[i][s] += __shfl_down_sync(0xffffffffu, part[i][s], off);
        if (lane == 0) {
#pragma unroll
            for (int i = 0; i < 4; i++) {
                const float scale = 0.0625f;   // 1/sqrt(256)
                float m = -1e30f;
#pragma unroll
                for (int s = 0; s < 8; s++) m = fmaxf(m, part[i][s] * scale);
                float e[8], sum = 0.f;
#pragma unroll
                for (int s = 0; s < 8; s++) { e[s] = __expf(part[i][s] * scale - m); sum += e[s]; }
                float inv = 1.f / sum;
                int nl = warp * 16 + g * 4 + i;
#pragma unroll
                for (int s = 0; s < 8; s++) {
                    float p = e[s] * inv + 1e-8f;
                    ps[nl * 8 + s] = p;
                    csum[s] += p;
                }
            }
        }
    }
    if (lane == 0) {
#pragma unroll
        for (int s = 0; s < 8; s++) atomicAdd(&g_colsum[b * 8 + s], csum[s]);
    }
    __syncthreads();

    // phase 2: p^T v
    int d = tid;
    float acc[8] = {};
    const float* vb = g_v + ((size_t)(b * Nv + n0)) * 256;
    for (int n = 0; n < 128; n++) {
        float vv = vb[(size_t)n * 256 + d];
#pragma unroll
        for (int s = 0; s < 8; s++) acc[s] += ps[n * 8 + s] * vv;
    }
#pragma unroll
    for (int s = 0; s < 8; s++) atomicAdd(&g_upd[(b * 8 + s) * 256 + d], acc[s]);
}

// ---------------- divide updates by colsum ----------------
__global__ void finalize_upd_kernel() {
    int i = blockIdx.x * 256 + threadIdx.x;
    g_upd[i] = g_upd[i] / g_colsum[i >> 8];
}

// ---------------- small GEMM: C[M,N] = A[M,K] @ op(B) + bias ----------------
template<bool TRANSB, bool RELU, bool ACCUM>
__global__ __launch_bounds__(256)
void gemm64_kernel(const float* __restrict__ A, const float* __restrict__ Bm,
                   const float* __restrict__ bias, float* __restrict__ C,
                   int M, int N, int K) {
    __shared__ float As[8 * 68];
    __shared__ float Bs[8 * 68];
    int bm = blockIdx.y * 64, bn = blockIdx.x * 64;
    int tid = threadIdx.x;
    int ty = tid >> 4, tx = tid & 15;
    float acc[4][4] = {};
    for (int k0 = 0; k0 < K; k0 += 8) {
        if (tid < 128) {
            int row = tid >> 1, part = tid & 1;
            float4 av = *(const float4*)(A + (size_t)(bm + row) * K + k0 + part * 4);
            int kk = part * 4;
            As[(kk + 0) * 68 + row] = av.x;
            As[(kk + 1) * 68 + row] = av.y;
            As[(kk + 2) * 68 + row] = av.z;
            As[(kk + 3) * 68 + row] = av.w;
        } else {
            int t2 = tid - 128;
            if (TRANSB) {
                int n = t2 >> 1, part = t2 & 1;
                float4 bv = *(const float4*)(Bm + (size_t)(bn + n) * K + k0 + part * 4);
                int kk = part * 4;
                Bs[(kk + 0) * 68 + n] = bv.x;
                Bs[(kk + 1) * 68 + n] = bv.y;
                Bs[(kk + 2) * 68 + n] = bv.z;
                Bs[(kk + 3) * 68 + n] = bv.w;
            } else {
                int kk = t2 >> 4, q = t2 & 15;
                float4 bv = *(const float4*)(Bm + (size_t)(k0 + kk) * N + bn + q * 4);
                *(float4*)(Bs + kk * 68 + q * 4) = bv;
            }
        }
        __syncthreads();
#pragma unroll
        for (int kk = 0; kk < 8; kk++) {
            float4 a = *(const float4*)(As + kk * 68 + ty * 4);
            float4 bq = *(const float4*)(Bs + kk * 68 + tx * 4);
            float av[4] = {a.x, a.y, a.z, a.w};
            float bw[4] = {bq.x, bq.y, bq.z, bq.w};
#pragma unroll
            for (int i = 0; i < 4; i++)
#pragma unroll
                for (int j = 0; j < 4; j++)
                    acc[i][j] += av[i] * bw[j];
        }
        __syncthreads();
    }
#pragma unroll
    for (int i = 0; i < 4; i++) {
        int r = bm + ty * 4 + i;
#pragma unroll
        for (int j = 0; j < 4; j++) {
            int c = bn + tx * 4 + j;
            float v = acc[i][j] + bias[c];
            if (RELU) v = fmaxf(v, 0.f);
            if (ACCUM) C[(size_t)r * N + c] += v;
            else       C[(size_t)r * N + c] = v;
        }
    }
}

// ---------------- GRU elementwise combine ----------------
__global__ void gru_combine_kernel() {
    int i = blockIdx.x * 256 + threadIdx.x;
    int row = i >> 8, d = i & 255;
    const float* gx = g_gx + row * 768;
    const float* gh = g_gh + row * 768;
    float r  = 1.f / (1.f + __expf(-(gx[d] + gh[d])));
    float z  = 1.f / (1.f + __expf(-(gx[256 + d] + gh[256 + d])));
    float nn = tanhf(gx[512 + d] + r * gh[512 + d]);
    float h  = g_sln[i];
    g_slots[i] = (1.f - z) * nn + z * h;
}

// ---------------- LN of slots -> y ----------------
__global__ void ln_y_kernel() {
    int row = blockIdx.x, t = threadIdx.x;
    float v = g_slots[row * 256 + t];
    g_y[row * 256 + t] = block_ln256(v);
}

// ---------------- copy out ----------------
__global__ void copy_out_kernel(float* __restrict__ out) {
    int i = blockIdx.x * 256 + threadIdx.x;
    out[i] = g_slots[i];
}

// =====================================================================
extern "C" void kernel_launch(void* const* d_in, const int* in_sizes, int n_in,
                              void* d_out, int out_size) {
    (void)in_sizes; (void)n_in; (void)out_size;
    const float* inputs = (const float*)d_in[0];
    const float* noise  = (const float*)d_in[1];
    const float* Wk     = (const float*)d_in[2];
    const float* Wv     = (const float*)d_in[3];
    const float* Wq     = (const float*)d_in[4];
    const float* mu     = (const float*)d_in[5];
    const float* ls     = (const float*)d_in[6];
    const float* wih    = (const float*)d_in[7];
    const float* whh    = (const float*)d_in[8];
    const float* bih    = (const float*)d_in[9];
    const float* bhh    = (const float*)d_in[10];
    const float* w1     = (const float*)d_in[11];
    const float* b1     = (const float*)d_in[12];
    const float* w2     = (const float*)d_in[13];
    const float* b2     = (const float*)d_in[14];

    float *p_upd, *p_sln, *p_y, *p_h1, *p_gx, *p_gh, *p_slots;
    cudaGetSymbolAddress((void**)&p_upd,   g_upd);
    cudaGetSymbolAddress((void**)&p_sln,   g_sln);
    cudaGetSymbolAddress((void**)&p_y,     g_y);
    cudaGetSymbolAddress((void**)&p_h1,    g_h1);
    cudaGetSymbolAddress((void**)&p_gx,    g_gx);
    cudaGetSymbolAddress((void**)&p_gh,    g_gh);
    cudaGetSymbolAddress((void**)&p_slots, g_slots);

    ln_stats_kernel<<<ROWSv / 8, 256>>>(inputs);
    wsum_kernel<<<1, 512>>>(Wk, Wv);
    transpose_w_kernel<<<dim3(16, 16), dim3(32, 8)>>>(Wk, Wv);
    proj_mma_kernel<<<dim3(4, 1024), 256>>>(inputs);
    init_slots_kernel<<<256, 256>>>(noise, mu, ls);

    for (int it = 0; it < 3; it++) {
        slot_ln_q_kernel<<<256, 256>>>(Wq);
        zero_kernel<<<256, 256>>>();
        attn_upd_kernel<<<dim3(32, 32), 256>>>();
        finalize_upd_kernel<<<256, 256>>>();
        gemm64_kernel<true,  false, false><<<dim3(12, 4), 256>>>(p_upd, wih, bih, p_gx, 256, 768, 256);
        gemm64_kernel<true,  false, false><<<dim3(12, 4), 256>>>(p_sln, whh, bhh, p_gh, 256, 768, 256);
        gru_combine_kernel<<<256, 256>>>();
        ln_y_kernel<<<256, 256>>>();
        gemm64_kernel<false, true,  false><<<dim3(8, 4),  256>>>(p_y,  w1, b1, p_h1,    256, 512, 256);
        gemm64_kernel<false, false, true ><<<dim3(4, 4),  256>>>(p_h1, w2, b2, p_slots, 256, 256, 512);
    }
    copy_out_kernel<<<256, 256>>>((float*)d_out);
}

// round 9
// speedup vs baseline: 1.6682x; 1.5088x over previous
#include <cuda_runtime.h>
#include <math.h>
#include <stdint.h>

// Problem constants
#define Bv    32
#define Nv    4096
#define INPv  512
#define Sv    8
#define Dv    256
#define Hv    512
#define ROWSv (Bv*Nv)   // 131072
#define SRv   (Bv*Sv)   // 256

// ---------------- scratch (static device globals; no allocs allowed) ----------------
__device__ __align__(16) float g_k[33554432];      // [ROWS][256]  128 MB
__device__ __align__(16) float g_v[33554432];      // [ROWS][256]  128 MB
__device__ __align__(16) float g_stats[262144];    // [ROWS][2] mean,rstd
__device__ __align__(16) float g_wsum[512];        // colsum of [Wk|Wv]
__device__ __align__(16) float g_wt[262144];       // transposed fused W: [512 n][512 k]
__device__ __align__(16) float g_slots[65536];     // [256][256]
__device__ __align__(16) float g_sln[65536];
__device__ __align__(16) float g_q[65536];
__device__ __align__(16) float g_upd[65536];
__device__ __align__(16) float g_colsum[256];
__device__ __align__(16) float g_gx[196608];       // [256][768]
__device__ __align__(16) float g_gh[196608];
__device__ __align__(16) float g_h1[131072];       // [256][512]
__device__ __align__(16) float g_y[65536];

__device__ __forceinline__ uint32_t smem_u32(const void* p) {
    uint32_t a;
    asm("{ .reg .u64 t; cvta.to.shared.u64 t, %1; cvt.u32.u64 %0, t; }" : "=r"(a) : "l"(p));
    return a;
}
__device__ __forceinline__ void cpasync16(uint32_t d, const void* g) {
    asm volatile("cp.async.cg.shared.global [%0], [%1], 16;" :: "r"(d), "l"(g));
}
#define CP_COMMIT() asm volatile("cp.async.commit_group;" ::: "memory")
#define CP_WAIT0()  asm volatile("cp.async.wait_group 0;" ::: "memory")

// ---------------- LN stats: mean/rstd per input row of 512 ----------------
__global__ void ln_stats_kernel(const float* __restrict__ X) {
    int warp = threadIdx.x >> 5, lane = threadIdx.x & 31;
    int row  = blockIdx.x * 8 + warp;
    const float* xr = X + (size_t)row * INPv;
    float s = 0.f, s2 = 0.f;
#pragma unroll
    for (int j = 0; j < 4; j++) {
        float4 v4 = *(const float4*)(xr + lane * 4 + 128 * j);
        s  += v4.x + v4.y + v4.z + v4.w;
        s2 += v4.x * v4.x + v4.y * v4.y + v4.z * v4.z + v4.w * v4.w;
    }
#pragma unroll
    for (int off = 16; off; off >>= 1) {
        s  += __shfl_down_sync(0xffffffffu, s,  off);
        s2 += __shfl_down_sync(0xffffffffu, s2, off);
    }
    if (!lane) {
        float m   = s * (1.f / INPv);
        float var = s2 * (1.f / INPv) - m * m;
        g_stats[row * 2]     = m;
        g_stats[row * 2 + 1] = rsqrtf(var + 1e-5f);
    }
}

// ---------------- column sums of Wk|Wv (parallel) ----------------
__global__ void wsum_kernel(const float* __restrict__ Wk, const float* __restrict__ Wv) {
    __shared__ float red[4][64];
    int b = blockIdx.x;                 // 8 blocks x 64 cols
    int c0 = b * 64;
    int col = threadIdx.x & 63, part = threadIdx.x >> 6;
    const float* W = (c0 < 256) ? Wk : Wv;
    int cc = (c0 & 255) + col;
    float s = 0.f;
    for (int k = part * 128; k < part * 128 + 128; k++) s += W[k * 256 + cc];
    red[part][col] = s;
    __syncthreads();
    if (threadIdx.x < 64) {
        g_wsum[c0 + threadIdx.x] = red[0][threadIdx.x] + red[1][threadIdx.x]
                                 + red[2][threadIdx.x] + red[3][threadIdx.x];
    }
}

// ---------------- transpose fused weights: g_wt[n][k] = W[k][n] ----------------
__global__ void transpose_w_kernel(const float* __restrict__ Wk, const float* __restrict__ Wv) {
    __shared__ float t[32][33];
    int n0 = blockIdx.x * 32, k0 = blockIdx.y * 32;
    int tx = threadIdx.x, ty = threadIdx.y;     // (32, 8)
    const float* W = (n0 < 256) ? Wk : Wv;
    int col0 = n0 & 255;
#pragma unroll
    for (int j = 0; j < 4; j++) {
        int k = k0 + ty + 8 * j;
        t[ty + 8 * j][tx] = W[(size_t)k * 256 + col0 + tx];
    }
    __syncthreads();
#pragma unroll
    for (int j = 0; j < 4; j++) {
        int n = n0 + ty + 8 * j;
        g_wt[(size_t)n * 512 + k0 + tx] = t[tx][ty + 8 * j];
    }
}

// ---------------- tf32 mma.sync projection with cp.async pipeline ----------------
// CTA 128(M)x128(N), K chunks of 32, double-buffered cp.async.
// Fragment k-remap: slots (q,q+4) <- smem cols (2q,2q+1) => LDS.64 loads.
#define PITCH 36
#define ABYTES (128 * PITCH * 4)      // 18432 per buffer

__global__ __launch_bounds__(256, 2)
void proj_mma_kernel(const float* __restrict__ X) {
    extern __shared__ char dsm[];
    uint32_t sb = smem_u32(dsm);
    int n0   = blockIdx.x * 128;
    int row0 = blockIdx.y * 128;
    int tid  = threadIdx.x;
    int wid  = tid >> 5, lane = tid & 31;
    int warp_m = wid >> 2, warp_n = wid & 3;
    int mb = warp_m * 64, nb = warp_n * 32;
    int grp = lane >> 2, q = lane & 3;
    int lr = tid >> 3, lc = tid & 7;    // load row-base / float4 slot

    float acc[4][4][4];
#pragma unroll
    for (int f = 0; f < 4; f++)
#pragma unroll
        for (int g = 0; g < 4; g++)
#pragma unroll
            for (int c = 0; c < 4; c++) acc[f][g][c] = 0.f;

    // issue chunk c into buffer buf
    auto issue = [&](int c, int buf) {
        const float* gA = X    + (size_t)(row0 + lr) * 512 + c * 32 + lc * 4;
        const float* gB = g_wt + (size_t)(n0   + lr) * 512 + c * 32 + lc * 4;
        uint32_t dA = sb + buf * ABYTES       + (lr * PITCH + lc * 4) * 4;
        uint32_t dB = sb + (2 + buf) * ABYTES + (lr * PITCH + lc * 4) * 4;
#pragma unroll
        for (int j = 0; j < 4; j++) {
            cpasync16(dA + j * 32 * PITCH * 4, gA + (size_t)j * 32 * 512);
            cpasync16(dB + j * 32 * PITCH * 4, gB + (size_t)j * 32 * 512);
        }
    };

    issue(0, 0);
    CP_COMMIT();

    int buf = 0;
    for (int c = 0; c < 16; c++) {
        CP_WAIT0();
        __syncthreads();
        if (c < 15) { issue(c + 1, buf ^ 1); CP_COMMIT(); }

        const float* As = (const float*)(dsm + buf * ABYTES);
        const float* Bs = (const float*)(dsm + (2 + buf) * ABYTES);
#pragma unroll
        for (int ks = 0; ks < 4; ks++) {
            float2 bfr[4];
#pragma unroll
            for (int g = 0; g < 4; g++)
                bfr[g] = *(const float2*)(Bs + (nb + g * 8 + grp) * PITCH + 8 * ks + 2 * q);
#pragma unroll
            for (int f = 0; f < 4; f++) {
                float2 ua = *(const float2*)(As + (mb + f * 16 + grp)     * PITCH + 8 * ks + 2 * q);
                float2 va = *(const float2*)(As + (mb + f * 16 + grp + 8) * PITCH + 8 * ks + 2 * q);
                uint32_t a0 = __float_as_uint(ua.x), a1 = __float_as_uint(va.x);
                uint32_t a2 = __float_as_uint(ua.y), a3 = __float_as_uint(va.y);
#pragma unroll
                for (int g = 0; g < 4; g++) {
                    asm volatile(
                        "mma.sync.aligned.m16n8k8.row.col.f32.tf32.tf32.f32 "
                        "{%0,%1,%2,%3}, {%4,%5,%6,%7}, {%8,%9}, {%0,%1,%2,%3};"
                        : "+f"(acc[f][g][0]), "+f"(acc[f][g][1]),
                          "+f"(acc[f][g][2]), "+f"(acc[f][g][3])
                        : "r"(a0), "r"(a1), "r"(a2), "r"(a3),
                          "r"(__float_as_uint(bfr[g].x)), "r"(__float_as_uint(bfr[g].y)));
                }
            }
        }
        buf ^= 1;
    }

    // epilogue: LN fold + store float2 pairs
#pragma unroll
    for (int f = 0; f < 4; f++) {
        int r0g = row0 + mb + f * 16 + grp;
        int r1g = r0g + 8;
        float m0 = g_stats[r0g * 2],     s0 = g_stats[r0g * 2 + 1];
        float m1 = g_stats[r1g * 2],     s1 = g_stats[r1g * 2 + 1];
        float mr0 = m0 * s0, mr1 = m1 * s1;
#pragma unroll
        for (int g = 0; g < 4; g++) {
            int nglob = n0 + nb + g * 8 + q * 2;
            float ws0 = g_wsum[nglob], ws1 = g_wsum[nglob + 1];
            float2 o0, o1;
            o0.x = s0 * acc[f][g][0] - mr0 * ws0;
            o0.y = s0 * acc[f][g][1] - mr0 * ws1;
            o1.x = s1 * acc[f][g][2] - mr1 * ws0;
            o1.y = s1 * acc[f][g][3] - mr1 * ws1;
            if (nglob < 256) {
                *(float2*)(g_k + (size_t)r0g * 256 + nglob) = o0;
                *(float2*)(g_k + (size_t)r1g * 256 + nglob) = o1;
            } else {
                *(float2*)(g_v + (size_t)r0g * 256 + nglob - 256) = o0;
                *(float2*)(g_v + (size_t)r1g * 256 + nglob - 256) = o1;
            }
        }
    }
}

// ---------------- slots init ----------------
__global__ void init_slots_kernel(const float* __restrict__ noise,
                                  const float* __restrict__ mu,
                                  const float* __restrict__ ls) {
    int i = blockIdx.x * 256 + threadIdx.x;   // 65536
    int d = i & 255;
    g_slots[i] = mu[d] + expf(ls[d]) * noise[i];
}

// ---------------- block LayerNorm over 256 (blockDim=256) ----------------
__device__ __forceinline__ float block_ln256(float v) {
    __shared__ float red[66];
    float s = v, s2 = v * v;
    int lane = threadIdx.x & 31, warp = threadIdx.x >> 5;
#pragma unroll
    for (int off = 16; off; off >>= 1) {
        s  += __shfl_down_sync(0xffffffffu, s,  off);
        s2 += __shfl_down_sync(0xffffffffu, s2, off);
    }
    if (!lane) { red[warp] = s; red[32 + warp] = s2; }
    __syncthreads();
    if (threadIdx.x == 0) {
        float ts = 0.f, t2 = 0.f;
#pragma unroll
        for (int i = 0; i < 8; i++) { ts += red[i]; t2 += red[32 + i]; }
        float m   = ts * (1.f / 256.f);
        float var = t2 * (1.f / 256.f) - m * m;
        red[64] = m;
        red[65] = rsqrtf(var + 1e-5f);
    }
    __syncthreads();
    return (v - red[64]) * red[65];
}

// ---------------- slots LN + q = s_ln @ Wq + zero accumulators ----------------
__global__ void slot_ln_q_kernel(const float* __restrict__ Wq) {
    __shared__ float sln[256];
    int row = blockIdx.x, t = threadIdx.x;
    float v  = g_slots[row * 256 + t];
    float nv = block_ln256(v);
    g_sln[row * 256 + t] = nv;
    sln[t] = nv;
    // zero accumulators for this iteration
    g_upd[row * 256 + t] = 0.f;
    if (t == 0) g_colsum[row] = 0.f;
    __syncthreads();
    float a0 = 0.f, a1 = 0.f, a2 = 0.f, a3 = 0.f;
#pragma unroll 2
    for (int k = 0; k < 256; k += 4) {
        a0 += sln[k]     * Wq[(k)     * 256 + t];
        a1 += sln[k + 1] * Wq[(k + 1) * 256 + t];
        a2 += sln[k + 2] * Wq[(k + 2) * 256 + t];
        a3 += sln[k + 3] * Wq[(k + 3) * 256 + t];
    }
    g_q[row * 256 + t] = (a0 + a1) + (a2 + a3);
}

// ---------------- fused attention + updates ----------------
__global__ __launch_bounds__(256)
void attn_upd_kernel() {
    __shared__ float qs[2048];       // [8][256]
    __shared__ float ps[128 * 8];
    int b  = blockIdx.y;
    int n0 = blockIdx.x * 128;
    int tid = threadIdx.x;
    int warp = tid >> 5, lane = tid & 31;

    for (int i = tid; i < 2048; i += 256) qs[i] = g_q[(size_t)b * 2048 + i];
    __syncthreads();

    float csum[8] = {};
#pragma unroll
    for (int g = 0; g < 4; g++) {
        int nb = n0 + warp * 16 + g * 4;
        const float* k0p = g_k + ((size_t)(b * Nv + nb)) * 256;
        float part[4][8] = {};
#pragma unroll
        for (int j = 0; j < 8; j++) {
            int d = lane + 32 * j;
            float kv0 = k0p[d];
            float kv1 = k0p[256 + d];
            float kv2 = k0p[512 + d];
            float kv3 = k0p[768 + d];
#pragma unroll
            for (int s = 0; s < 8; s++) {
                float qv = qs[s * 256 + d];
                part[0][s] += kv0 * qv;
                part[1][s] += kv1 * qv;
                part[2][s] += kv2 * qv;
                part[3][s] += kv3 * qv;
            }
        }
#pragma unroll
        for (int i = 0; i < 4; i++)
#pragma unroll
            for (int s = 0; s < 8; s++)
#pragma unroll
                for (int off = 16; off; off >>= 1)
                    part[i][s] += __shfl_down_sync(0xffffffffu, part[i][s], off);
        if (lane == 0) {
#pragma unroll
            for (int i = 0; i < 4; i++) {
                const float scale = 0.0625f;   // 1/sqrt(256)
                float m = -1e30f;
#pragma unroll
                for (int s = 0; s < 8; s++) m = fmaxf(m, part[i][s] * scale);
                float e[8], sum = 0.f;
#pragma unroll
                for (int s = 0; s < 8; s++) { e[s] = __expf(part[i][s] * scale - m); sum += e[s]; }
                float inv = 1.f / sum;
                int nl = warp * 16 + g * 4 + i;
#pragma unroll
                for (int s = 0; s < 8; s++) {
                    float p = e[s] * inv + 1e-8f;
                    ps[nl * 8 + s] = p;
                    csum[s] += p;
                }
            }
        }
    }
    if (lane == 0) {
#pragma unroll
        for (int s = 0; s < 8; s++) atomicAdd(&g_colsum[b * 8 + s], csum[s]);
    }
    __syncthreads();

    // phase 2: p^T v
    int d = tid;
    float acc[8] = {};
    const float* vb = g_v + ((size_t)(b * Nv + n0)) * 256;
    for (int n = 0; n < 128; n++) {
        float vv = vb[(size_t)n * 256 + d];
#pragma unroll
        for (int s = 0; s < 8; s++) acc[s] += ps[n * 8 + s] * vv;
    }
#pragma unroll
    for (int s = 0; s < 8; s++) atomicAdd(&g_upd[(b * 8 + s) * 256 + d], acc[s]);
}

// ---------------- merged GRU gate GEMMs (gx and gh in one launch) ----------------
// path 0: gx = (upd/colsum) @ wih^T + bih ; path 1: gh = sln @ whh^T + bhh
__global__ __launch_bounds__(256)
void gru_gemm_kernel(const float* __restrict__ wih, const float* __restrict__ whh,
                     const float* __restrict__ bih, const float* __restrict__ bhh) {
    __shared__ float As[8 * 68];
    __shared__ float Bs[8 * 68];
    int path = blockIdx.x / 12;
    int bxl  = blockIdx.x - path * 12;
    const float* A    = path ? g_sln : g_upd;
    const float* Bm   = path ? whh   : wih;
    const float* bias = path ? bhh   : bih;
    float* C          = path ? g_gh  : g_gx;
    const int N = 768, K = 256;
    int bm = blockIdx.y * 64, bn = bxl * 64;
    int tid = threadIdx.x;
    int ty = tid >> 4, tx = tid & 15;

    float inv = 1.f;
    int arow = bm + (tid >> 1);
    if (tid < 128 && path == 0) inv = 1.f / g_colsum[arow];

    float acc[4][4] = {};
    for (int k0 = 0; k0 < K; k0 += 8) {
        if (tid < 128) {
            int row = tid >> 1, part = tid & 1;
            float4 av = *(const float4*)(A + (size_t)(bm + row) * K + k0 + part * 4);
            int kk = part * 4;
            As[(kk + 0) * 68 + row] = av.x * inv;
            As[(kk + 1) * 68 + row] = av.y * inv;
            As[(kk + 2) * 68 + row] = av.z * inv;
            As[(kk + 3) * 68 + row] = av.w * inv;
        } else {
            int t2 = tid - 128;
            int n = t2 >> 1, part = t2 & 1;
            float4 bv = *(const float4*)(Bm + (size_t)(bn + n) * K + k0 + part * 4);
            int kk = part * 4;
            Bs[(kk + 0) * 68 + n] = bv.x;
            Bs[(kk + 1) * 68 + n] = bv.y;
            Bs[(kk + 2) * 68 + n] = bv.z;
            Bs[(kk + 3) * 68 + n] = bv.w;
        }
        __syncthreads();
#pragma unroll
        for (int kk = 0; kk < 8; kk++) {
            float4 a = *(const float4*)(As + kk * 68 + ty * 4);
            float4 bq = *(const float4*)(Bs + kk * 68 + tx * 4);
            float av[4] = {a.x, a.y, a.z, a.w};
            float bw[4] = {bq.x, bq.y, bq.z, bq.w};
#pragma unroll
            for (int i = 0; i < 4; i++)
#pragma unroll
                for (int j = 0; j < 4; j++)
                    acc[i][j] += av[i] * bw[j];
        }
        __syncthreads();
    }
#pragma unroll
    for (int i = 0; i < 4; i++) {
        int r = bm + ty * 4 + i;
#pragma unroll
        for (int j = 0; j < 4; j++) {
            int c = bn + tx * 4 + j;
            C[(size_t)r * N + c] = acc[i][j] + bias[c];
        }
    }
}

// ---------------- small GEMM: C[M,N] = A[M,K] @ B + bias (B k-major) ----------------
template<bool RELU, bool ACCUM>
__global__ __launch_bounds__(256)
void gemm64_kernel(const float* __restrict__ A, const float* __restrict__ Bm,
                   const float* __restrict__ bias, float* __restrict__ C,
                   int M, int N, int K, float* __restrict__ out2) {
    __shared__ float As[8 * 68];
    __shared__ float Bs[8 * 68];
    int bm = blockIdx.y * 64, bn = blockIdx.x * 64;
    int tid = threadIdx.x;
    int ty = tid >> 4, tx = tid & 15;
    float acc[4][4] = {};
    for (int k0 = 0; k0 < K; k0 += 8) {
        if (tid < 128) {
            int row = tid >> 1, part = tid & 1;
            float4 av = *(const float4*)(A + (size_t)(bm + row) * K + k0 + part * 4);
            int kk = part * 4;
            As[(kk + 0) * 68 + row] = av.x;
            As[(kk + 1) * 68 + row] = av.y;
            As[(kk + 2) * 68 + row] = av.z;
            As[(kk + 3) * 68 + row] = av.w;
        } else {
            int t2 = tid - 128;
            int kk = t2 >> 4, q = t2 & 15;
            float4 bv = *(const float4*)(Bm + (size_t)(k0 + kk) * N + bn + q * 4);
            *(float4*)(Bs + kk * 68 + q * 4) = bv;
        }
        __syncthreads();
#pragma unroll
        for (int kk = 0; kk < 8; kk++) {
            float4 a = *(const float4*)(As + kk * 68 + ty * 4);
            float4 bq = *(const float4*)(Bs + kk * 68 + tx * 4);
            float av[4] = {a.x, a.y, a.z, a.w};
            float bw[4] = {bq.x, bq.y, bq.z, bq.w};
#pragma unroll
            for (int i = 0; i < 4; i++)
#pragma unroll
                for (int j = 0; j < 4; j++)
                    acc[i][j] += av[i] * bw[j];
        }
        __syncthreads();
    }
#pragma unroll
    for (int i = 0; i < 4; i++) {
        int r = bm + ty * 4 + i;
#pragma unroll
        for (int j = 0; j < 4; j++) {
            int c = bn + tx * 4 + j;
            float v = acc[i][j] + bias[c];
            if (RELU) v = fmaxf(v, 0.f);
            if (ACCUM) {
                float nv = C[(size_t)r * N + c] + v;
                C[(size_t)r * N + c] = nv;
                if (out2) out2[(size_t)r * N + c] = nv;
            } else {
                C[(size_t)r * N + c] = v;
            }
        }
    }
}

// ---------------- GRU combine + LN(y) fused ----------------
__global__ void gru_lny_kernel() {
    int row = blockIdx.x, t = threadIdx.x;
    int i = row * 256 + t;
    const float* gx = g_gx + row * 768;
    const float* gh = g_gh + row * 768;
    float r  = 1.f / (1.f + __expf(-(gx[t] + gh[t])));
    float z  = 1.f / (1.f + __expf(-(gx[256 + t] + gh[256 + t])));
    float nn = tanhf(gx[512 + t] + r * gh[512 + t]);
    float h  = (1.f - z) * nn + z * g_sln[i];
    g_slots[i] = h;
    g_y[i] = block_ln256(h);
}

// =====================================================================
extern "C" void kernel_launch(void* const* d_in, const int* in_sizes, int n_in,
                              void* d_out, int out_size) {
    (void)in_sizes; (void)n_in; (void)out_size;
    const float* inputs = (const float*)d_in[0];
    const float* noise  = (const float*)d_in[1];
    const float* Wk     = (const float*)d_in[2];
    const float* Wv     = (const float*)d_in[3];
    const float* Wq     = (const float*)d_in[4];
    const float* mu     = (const float*)d_in[5];
    const float* ls     = (const float*)d_in[6];
    const float* wih    = (const float*)d_in[7];
    const float* whh    = (const float*)d_in[8];
    const float* bih    = (const float*)d_in[9];
    const float* bhh    = (const float*)d_in[10];
    const float* w1     = (const float*)d_in[11];
    const float* b1     = (const float*)d_in[12];
    const float* w2     = (const float*)d_in[13];
    const float* b2     = (const float*)d_in[14];

    float *p_h1, *p_y, *p_slots;
    cudaGetSymbolAddress((void**)&p_h1,    g_h1);
    cudaGetSymbolAddress((void**)&p_y,     g_y);
    cudaGetSymbolAddress((void**)&p_slots, g_slots);

    cudaFuncSetAttribute(proj_mma_kernel,
                         cudaFuncAttributeMaxDynamicSharedMemorySize, 4 * ABYTES);

    ln_stats_kernel<<<ROWSv / 8, 256>>>(inputs);
    wsum_kernel<<<8, 256>>>(Wk, Wv);
    transpose_w_kernel<<<dim3(16, 16), dim3(32, 8)>>>(Wk, Wv);
    proj_mma_kernel<<<dim3(4, 1024), 256, 4 * ABYTES>>>(inputs);
    init_slots_kernel<<<256, 256>>>(noise, mu, ls);

    for (int it = 0; it < 3; it++) {
        slot_ln_q_kernel<<<256, 256>>>(Wq);
        attn_upd_kernel<<<dim3(32, 32), 256>>>();
        gru_gemm_kernel<<<dim3(24, 4), 256>>>(wih, whh, bih, bhh);
        gru_lny_kernel<<<256, 256>>>();
        gemm64_kernel<true,  false><<<dim3(8, 4), 256>>>(p_y,  w1, b1, p_h1,    256, 512, 256, nullptr);
        gemm64_kernel<false, true ><<<dim3(4, 4), 256>>>(p_h1, w2, b2, p_slots, 256, 256, 512,
                                                         (it == 2) ? (float*)d_out : nullptr);
    }
}